// round 9
// baseline (speedup 1.0000x reference)
#include <cuda_runtime.h>
#include <cstdint>
#include <cstddef>

// ---------------------------------------------------------------------------
// SNN, fp32-faithful with association ticket: K split into panels
// [0,512) and [512,1024); each panel a serial ascending-k fp32 FMA chain
// from zero; panel sums combined with one rounded add. Inner loop uses
// Blackwell packed fma.rn.f32x2 (per-lane IEEE RN -> bit-identical to the
// scalar chain, 2x FFMA issue throughput).
// Elementwise updates in the reference's left-to-right order.
// ---------------------------------------------------------------------------

#define NB 16384
#define NH 1024
#define NSTEPS 25
#define NO 10

// ----------------------------- device scratch ------------------------------
__device__ __align__(16) float g_spk1a[NB * NH];
__device__ __align__(16) float g_spk1b[NB * NH];
__device__ __align__(16) float g_spk2a[NB * NH];
__device__ __align__(16) float g_spk2b[NB * NH];
__device__ __align__(16) float g_mem1[NB * NH];
__device__ __align__(16) float g_mem2[NB * NH];
__device__ __align__(16) float g_cur1[NB * NH];
__device__ __align__(16) float g_cur2[NB * NH];
__device__ __align__(16) float g_ssum[NB * NH];

// --------------------------- f32x2 packed helpers ---------------------------
__device__ __forceinline__ uint64_t dup2(float x) {
    uint64_t d;
    asm("mov.b64 %0, {%1, %2};" : "=l"(d) : "f"(x), "f"(x));
    return d;
}
__device__ __forceinline__ uint64_t fma2(uint64_t a, uint64_t b, uint64_t c) {
    uint64_t d;
    asm("fma.rn.f32x2 %0, %1, %2, %3;" : "=l"(d) : "l"(a), "l"(b), "l"(c));
    return d;
}
__device__ __forceinline__ uint64_t add2(uint64_t a, uint64_t b) {
    uint64_t d;
    asm("add.rn.f32x2 %0, %1, %2;" : "=l"(d) : "l"(a), "l"(b));
    return d;
}
__device__ __forceinline__ float2 unpk2(uint64_t v) {
    float lo, hi;
    asm("mov.b64 {%0, %1}, %2;" : "=f"(lo), "=f"(hi) : "l"(v));
    return make_float2(lo, hi);
}

// ------------------------------- prep kernels ------------------------------
__global__ void init_state_kernel() {
    size_t i = (size_t)blockIdx.x * blockDim.x + threadIdx.x;
    g_mem1[i] = 0.f;
    g_mem2[i] = 0.f;
    g_ssum[i] = 0.f;
    g_spk1a[i] = 0.f;
    g_spk2a[i] = 0.f;
}

// ssum <- ssum / 25  (reference divides BEFORE the W3 matmul)
__global__ void div25_kernel(float* __restrict__ s) {
    size_t i = (size_t)blockIdx.x * blockDim.x + threadIdx.x;
    s[i] = __fdiv_rn(s[i], 25.0f);
}

// ------------------------------- GEMM kernel -------------------------------
// C[m,n] = sum_k A[m,k]*B[n,k]: panels [0,512),[512,1024), serial within,
// one rounded add to combine. Tile 128x128, k-step 8, 256 threads,
// 8x8 microtile, f32x2 packed FMA.

#define SMP 132   // smem row pitch (floats), padded

// MODE 0: outC = tot + biasA[n]
// MODE 1: mem = 0.5*mem + cur + tot + biasA - reset; spike; [DOSUM] ssum += s
template <int MODE, int DOSUM>
__global__ void __launch_bounds__(256, 1)
f32gemm_kernel(const float* __restrict__ Ag, const float* __restrict__ Bg,
               const float* __restrict__ biasA,
               float* __restrict__ memBuf, const float* __restrict__ curBuf,
               float* __restrict__ spkOut,
               float* __restrict__ ssum, float* __restrict__ outC) {
    __shared__ __align__(16) float sA[2][8][SMP];
    __shared__ __align__(16) float sB[2][8][SMP];

    const int tid = threadIdx.x;
    const int tm  = tid >> 4;    // 0..15
    const int tn  = tid & 15;    // 0..15
    const int m0  = blockIdx.y * 128;
    const int n0  = blockIdx.x * 128;

    // packed accumulators: acc2[i][j2] = (acc[i][2j2], acc[i][2j2+1])
    uint64_t tot2[8][4];   // running panel-folded total
    uint64_t acc2[8][4];   // current panel partial
#pragma unroll
    for (int i = 0; i < 8; i++)
#pragma unroll
        for (int j = 0; j < 4; j++) { tot2[i][j] = 0ull; acc2[i][j] = 0ull; }

    const int nk = 128;   // 1024 / 8

    const int lrow = tid >> 1;        // 0..127
    const int lc4  = (tid & 1) * 4;   // 0 or 4
    float4 ra, rb;

    auto gload = [&](int kt) {
        const int k0 = kt * 8 + lc4;
        ra = *(const float4*)(Ag + (size_t)(m0 + lrow) * NH + k0);
        rb = *(const float4*)(Bg + (size_t)(n0 + lrow) * NH + k0);
    };
    auto sts = [&](int b) {
        sA[b][lc4 + 0][lrow] = ra.x;
        sA[b][lc4 + 1][lrow] = ra.y;
        sA[b][lc4 + 2][lrow] = ra.z;
        sA[b][lc4 + 3][lrow] = ra.w;
        sB[b][lc4 + 0][lrow] = rb.x;
        sB[b][lc4 + 1][lrow] = rb.y;
        sB[b][lc4 + 2][lrow] = rb.z;
        sB[b][lc4 + 3][lrow] = rb.w;
    };

    gload(0);
    sts(0);
    __syncthreads();

    for (int kt = 0; kt < nk; kt++) {
        const int b = kt & 1;
        if (kt + 1 < nk) gload(kt + 1);

#pragma unroll
        for (int kk = 0; kk < 8; kk++) {
            float4 a0 = *(const float4*)&sA[b][kk][tm * 8];
            float4 a1 = *(const float4*)&sA[b][kk][tm * 8 + 4];
            // B pairs read directly as packed f32x2 (little-endian layout
            // of consecutive floats == packed lanes)
            ulonglong2 bq0 = *(const ulonglong2*)&sB[b][kk][tn * 8];
            ulonglong2 bq1 = *(const ulonglong2*)&sB[b][kk][tn * 8 + 4];
            uint64_t bp[4] = {bq0.x, bq0.y, bq1.x, bq1.y};
            float av[8] = {a0.x, a0.y, a0.z, a0.w, a1.x, a1.y, a1.z, a1.w};
#pragma unroll
            for (int i = 0; i < 8; i++) {
                uint64_t ad = dup2(av[i]);
#pragma unroll
                for (int j = 0; j < 4; j++)
                    acc2[i][j] = fma2(ad, bp[j], acc2[i][j]);
            }
        }

        // panel boundaries: k = 512 (kt 63) and k = 1024 (kt 127)
        if (kt == 63 || kt == 127) {
#pragma unroll
            for (int i = 0; i < 8; i++)
#pragma unroll
                for (int j = 0; j < 4; j++) {
                    tot2[i][j] = add2(tot2[i][j], acc2[i][j]);
                    acc2[i][j] = 0ull;
                }
        }

        __syncthreads();
        if (kt + 1 < nk) sts(b ^ 1);
        __syncthreads();
    }

    // ------------------------------ epilogue -------------------------------
#pragma unroll
    for (int i = 0; i < 8; i++) {
        const int row = m0 + tm * 8 + i;
        const int col0 = n0 + tn * 8;
        const size_t off = (size_t)row * NH + col0;
#pragma unroll
        for (int j2 = 0; j2 < 4; j2++) {
            float2 dv = unpk2(tot2[i][j2]);
#pragma unroll
            for (int h = 0; h < 2; h++) {
                const int j = 2 * j2 + h;
                const int c = col0 + j;
                float d = (h == 0) ? dv.x : dv.y;
                if (MODE == 0) {
                    outC[off + j] = __fadd_rn(d, biasA[c]);
                } else {
                    // reference order:
                    //   mem = ((((0.5*mem) + cur) + d) + bias) - reset(prev)
                    float mo = memBuf[off + j];
                    float reset = (mo > 1.0f) ? 1.0f : 0.0f;
                    float v = __fadd_rn(__fmul_rn(0.5f, mo), curBuf[off + j]);
                    v = __fadd_rn(v, d);
                    v = __fadd_rn(v, biasA[c]);
                    v = __fsub_rn(v, reset);
                    memBuf[off + j] = v;
                    float s = (v > 1.0f) ? 1.0f : 0.0f;
                    spkOut[off + j] = s;
                    if (DOSUM) ssum[off + j] = __fadd_rn(ssum[off + j], s);
                }
            }
        }
    }
}

// ------------------------------ output kernel ------------------------------
// out[r][o] = serial-k fma over t[r][k]*W3[o][k], then + b3[o].
__global__ void out_kernel(const float* __restrict__ t,
                           const float* __restrict__ W3,
                           const float* __restrict__ b3,
                           float* __restrict__ out) {
    int idx = blockIdx.x * blockDim.x + threadIdx.x;   // 0 .. NB*NO-1
    if (idx >= NB * NO) return;
    int row = idx / NO;
    int o   = idx - row * NO;
    const float* tr = t  + (size_t)row * NH;
    const float* wr = W3 + (size_t)o * NH;
    float acc = 0.f;
#pragma unroll 8
    for (int k = 0; k < NH; k++)
        acc = fmaf(__ldg(&tr[k]), __ldg(&wr[k]), acc);
    out[idx] = __fadd_rn(acc, b3[o]);
}

// ------------------------------- host launch -------------------------------
extern "C" void kernel_launch(void* const* d_in, const int* in_sizes, int n_in,
                              void* d_out, int out_size) {
    const float* x   = (const float*)d_in[0];
    const float* W1  = (const float*)d_in[1];
    const float* b1  = (const float*)d_in[2];
    const float* V1w = (const float*)d_in[3];
    const float* V1b = (const float*)d_in[4];
    const float* W2  = (const float*)d_in[5];
    const float* b2  = (const float*)d_in[6];
    const float* V2w = (const float*)d_in[7];
    const float* V2b = (const float*)d_in[8];
    const float* W3  = (const float*)d_in[9];
    const float* b3  = (const float*)d_in[10];
    float* out = (float*)d_out;

    void* p;
    float *spk1a, *spk1b, *spk2a, *spk2b, *mem1, *mem2, *cur1, *cur2, *ssum;
    cudaGetSymbolAddress(&p, g_spk1a); spk1a = (float*)p;
    cudaGetSymbolAddress(&p, g_spk1b); spk1b = (float*)p;
    cudaGetSymbolAddress(&p, g_spk2a); spk2a = (float*)p;
    cudaGetSymbolAddress(&p, g_spk2b); spk2b = (float*)p;
    cudaGetSymbolAddress(&p, g_mem1);  mem1  = (float*)p;
    cudaGetSymbolAddress(&p, g_mem2);  mem2  = (float*)p;
    cudaGetSymbolAddress(&p, g_cur1);  cur1  = (float*)p;
    cudaGetSymbolAddress(&p, g_cur2);  cur2  = (float*)p;
    cudaGetSymbolAddress(&p, g_ssum);  ssum  = (float*)p;

    const int nElem = NB * NH;
    init_state_kernel<<<nElem / 256, 256>>>();

    dim3 grid(NH / 128, NB / 128);   // (8, 128)
    dim3 block(256);

    // cur1 = x @ W1^T + b1
    f32gemm_kernel<0, 0><<<grid, block>>>(x, W1, b1,
                                          nullptr, nullptr, nullptr,
                                          nullptr, cur1);

    for (int st = 0; st < NSTEPS; st++) {
        const float* s1in = (st & 1) ? spk1b : spk1a;
        float*      s1out = (st & 1) ? spk1a : spk1b;
        const float* s2in = (st & 1) ? spk2b : spk2a;
        float*      s2out = (st & 1) ? spk2a : spk2b;

        // layer 1: mem1 = 0.5*mem1 + cur1 + s1in@V1w^T + V1b - reset; spike
        f32gemm_kernel<1, 0><<<grid, block>>>(s1in, V1w, V1b,
                                              mem1, cur1, s1out,
                                              nullptr, nullptr);

        // cur2 = s1out @ W2^T + b2  (separately rounded)
        f32gemm_kernel<0, 0><<<grid, block>>>(s1out, W2, b2,
                                              nullptr, nullptr, nullptr,
                                              nullptr, cur2);

        // layer 2: mem2 = 0.5*mem2 + cur2 + s2in@V2w^T + V2b - reset;
        //          spike; ssum += spike
        f32gemm_kernel<1, 1><<<grid, block>>>(s2in, V2w, V2b,
                                              mem2, cur2, s2out,
                                              ssum, nullptr);
    }

    // t = ssum/25 (rounded first), then out = t@W3^T + b3
    div25_kernel<<<nElem / 256, 256>>>(ssum);
    out_kernel<<<(NB * NO + 255) / 256, 256>>>(ssum, W3, b3, out);
}